// round 16
// baseline (speedup 1.0000x reference)
#include <cuda_runtime.h>
#include <cuda_bf16.h>
#include <cstdint>
#include <cstddef>

#define BATCH 8
#define TLEN  4096
#define PDIM  1024
#define RDIM  128
#define MROWS (BATCH*TLEN)
#define SCALE 0.08838834764831845f
#define EPS_V 1e-6f
#define NCHUNK 8
#define TCHUNK (TLEN / NCHUNK)          // 512
#define TPC    (32 / NCHUNK)            // 4 M-tiles per batch per chunk

// scratch (device globals; no allocation allowed)
__device__ float g_u[(size_t)MROWS * RDIM];
__device__ float g_a[(size_t)MROWS * RDIM];
__device__ float g_s[(size_t)MROWS * RDIM];
__device__ float g_state[(size_t)BATCH * RDIM];   // chunk-boundary w

__device__ __forceinline__ unsigned f2tf(float x) {
    unsigned r; asm("cvt.rna.tf32.f32 %0, %1;" : "=r"(r) : "f"(x)); return r;
}
__device__ __forceinline__ void mma_tf32(float* c, const unsigned* a, const unsigned* b) {
    asm volatile(
        "mma.sync.aligned.m16n8k8.row.col.f32.tf32.tf32.f32 "
        "{%0,%1,%2,%3},{%4,%5,%6,%7},{%8,%9},{%0,%1,%2,%3};"
        : "+f"(c[0]), "+f"(c[1]), "+f"(c[2]), "+f"(c[3])
        : "r"(a[0]), "r"(a[1]), "r"(a[2]), "r"(a[3]), "r"(b[0]), "r"(b[1]));
}

#define BM 128
#define BN 128
#define BK 32
#define ASTRIDE 36
#define BSTRIDE 136
#define ASTG (BM * ASTRIDE)
#define BSTG (BK * BSTRIDE)
#define STGW (ASTG + BSTG)
#define RS   132
#define SMEM_BYTES_FUSED (2 * 128 * RS * 4)        // 135168
#define SMEM_BYTES_OUT   (2 * 128 * RS * 4)        // 135168

// ---------------- gk_au: long-K producer (a and u), time-chunked ----------------
template <int MODE>
__device__ __forceinline__ void gemm_body_longk(
    const float* __restrict__ A, const float* __restrict__ A2,
    const float* __restrict__ Bm, const float* __restrict__ W,
    const float* __restrict__ bias, float* __restrict__ C,
    unsigned* sm, int bx) {

    const int tid  = threadIdx.x;
    const int wid  = tid >> 5;
    const int lane = tid & 31;
    const int grp  = lane >> 2;
    const int qid  = lane & 3;
    const int wm   = (wid & 3) * 32;
    const int wn   = (wid >> 2) * 64;
    const size_t m0 = (size_t)bx * BM;
    const int lda = PDIM, ldb = RDIM, ldc = RDIM;

    float acc[2][8][4];
#pragma unroll
    for (int mt = 0; mt < 2; mt++)
#pragma unroll
        for (int nt = 0; nt < 8; nt++)
#pragma unroll
            for (int i = 0; i < 4; i++) acc[mt][nt][i] = 0.0f;

    const int NK = PDIM / BK;   // 32
    float4 ra[4], rf[4], rb[4];

    int aRow[4], aC4[4], bK[4], bN[4];
#pragma unroll
    for (int i = 0; i < 4; i++) {
        int idx = tid + i * 256;
        aRow[i] = idx >> 3;  aC4[i] = (idx & 7) << 2;
        bK[i]   = idx >> 5;  bN[i]  = (idx & 31) << 2;
    }

    auto ldg = [&](int kc) {
#pragma unroll
        for (int i = 0; i < 4; i++) {
            size_t aoff = (m0 + aRow[i]) * (size_t)lda + kc * BK + aC4[i];
            ra[i] = *(const float4*)(A + aoff);
            if (MODE == 1) rf[i] = *(const float4*)(A2 + aoff);
            size_t boff = (size_t)(kc * BK + bK[i]) * (size_t)ldb + bN[i];
            rb[i] = *(const float4*)(Bm + boff);
        }
    };
    auto sts = [&](int stg) {
        unsigned* As = sm + stg * STGW;
        unsigned* Bs = As + ASTG;
#pragma unroll
        for (int i = 0; i < 4; i++) {
            float4 v = ra[i];
            if (MODE == 1) {
                v.x *= rf[i].x * SCALE; v.y *= rf[i].y * SCALE;
                v.z *= rf[i].z * SCALE; v.w *= rf[i].w * SCALE;
            }
            *(uint4*)&As[aRow[i] * ASTRIDE + aC4[i]] =
                make_uint4(f2tf(v.x), f2tf(v.y), f2tf(v.z), f2tf(v.w));
            float4 w = rb[i];
            *(uint4*)&Bs[bK[i] * BSTRIDE + bN[i]] =
                make_uint4(f2tf(w.x), f2tf(w.y), f2tf(w.z), f2tf(w.w));
        }
    };
    auto compute = [&](int stg) {
        const unsigned* Ab = sm + stg * STGW + wm * ASTRIDE;
        const unsigned* Bb = sm + stg * STGW + ASTG + wn;
#pragma unroll
        for (int ks = 0; ks < 4; ks++) {
            const int k = ks * 8;
            unsigned af[2][4];
#pragma unroll
            for (int mt = 0; mt < 2; mt++) {
                const unsigned* p = Ab + (mt * 16 + grp) * ASTRIDE + k + qid;
                af[mt][0] = p[0];
                af[mt][1] = p[8 * ASTRIDE];
                af[mt][2] = p[4];
                af[mt][3] = p[8 * ASTRIDE + 4];
            }
            unsigned bf[8][2];
#pragma unroll
            for (int nt = 0; nt < 8; nt++) {
                const unsigned* p = Bb + (k + qid) * BSTRIDE + nt * 8 + grp;
                bf[nt][0] = p[0];
                bf[nt][1] = p[4 * BSTRIDE];
            }
#pragma unroll
            for (int mt = 0; mt < 2; mt++)
#pragma unroll
                for (int nt = 0; nt < 8; nt++)
                    mma_tf32(acc[mt][nt], af[mt], bf[nt]);
        }
    };

    ldg(0);
    sts(0);
    __syncthreads();
    for (int kc = 0; kc < NK; ++kc) {
        int cur = kc & 1;
        if (kc + 1 < NK) ldg(kc + 1);
        compute(cur);
        if (kc + 1 < NK) sts(cur ^ 1);
        __syncthreads();
    }

    if (MODE == 0) {
        // fused phase 2: C = clip(sigmoid(r @ W + bias))
        unsigned* r_s = sm;
        unsigned* W_s = sm + 128 * RS;
#pragma unroll
        for (int mt = 0; mt < 2; mt++) {
#pragma unroll
            for (int nt = 0; nt < 8; nt++) {
                int row = wm + mt * 16 + grp;
                int col = wn + nt * 8 + 2 * qid;
                r_s[row * RS + col]           = f2tf(acc[mt][nt][0]);
                r_s[row * RS + col + 1]       = f2tf(acc[mt][nt][1]);
                r_s[(row + 8) * RS + col]     = f2tf(acc[mt][nt][2]);
                r_s[(row + 8) * RS + col + 1] = f2tf(acc[mt][nt][3]);
            }
        }
#pragma unroll
        for (int i = 0; i < 16; i++) {
            int idx = tid + i * 256;
            int row = idx >> 5;
            int c4  = (idx & 31) << 2;
            float4 v = *(const float4*)(W + row * RDIM + c4);
            *(uint4*)&W_s[row * RS + c4] =
                make_uint4(f2tf(v.x), f2tf(v.y), f2tf(v.z), f2tf(v.w));
        }
        __syncthreads();

        float acc2[2][8][4];
#pragma unroll
        for (int mt = 0; mt < 2; mt++)
#pragma unroll
            for (int nt = 0; nt < 8; nt++)
#pragma unroll
                for (int i = 0; i < 4; i++) acc2[mt][nt][i] = 0.0f;

#pragma unroll
        for (int ks = 0; ks < 16; ks++) {
            const int k = ks * 8;
            unsigned af[2][4];
#pragma unroll
            for (int mt = 0; mt < 2; mt++) {
                const unsigned* p = r_s + (wm + mt * 16 + grp) * RS + k + qid;
                af[mt][0] = p[0];
                af[mt][1] = p[8 * RS];
                af[mt][2] = p[4];
                af[mt][3] = p[8 * RS + 4];
            }
            unsigned bf[8][2];
#pragma unroll
            for (int nt = 0; nt < 8; nt++) {
                const unsigned* p = W_s + (k + qid) * RS + wn + nt * 8 + grp;
                bf[nt][0] = p[0];
                bf[nt][1] = p[4 * RS];
            }
#pragma unroll
            for (int mt = 0; mt < 2; mt++)
#pragma unroll
                for (int nt = 0; nt < 8; nt++)
                    mma_tf32(acc2[mt][nt], af[mt], bf[nt]);
        }
#pragma unroll
        for (int mt = 0; mt < 2; mt++) {
#pragma unroll
            for (int nt = 0; nt < 8; nt++) {
                int row = wm + mt * 16 + grp;
                int col = wn + nt * 8 + 2 * qid;
                float b0 = bias[col], b1 = bias[col + 1];
                float v0 = 1.0f / (1.0f + __expf(-(acc2[mt][nt][0] + b0)));
                float v1 = 1.0f / (1.0f + __expf(-(acc2[mt][nt][1] + b1)));
                float v2 = 1.0f / (1.0f + __expf(-(acc2[mt][nt][2] + b0)));
                float v3 = 1.0f / (1.0f + __expf(-(acc2[mt][nt][3] + b1)));
                v0 = fminf(fmaxf(v0, 0.01f), 0.995f);
                v1 = fminf(fmaxf(v1, 0.01f), 0.995f);
                v2 = fminf(fmaxf(v2, 0.01f), 0.995f);
                v3 = fminf(fmaxf(v3, 0.01f), 0.995f);
                size_t g0 = (m0 + row) * (size_t)ldc + col;
                size_t g2 = (m0 + row + 8) * (size_t)ldc + col;
                *(float2*)(C + g0) = make_float2(v0, v1);
                *(float2*)(C + g2) = make_float2(v2, v3);
            }
        }
    } else {
#pragma unroll
        for (int mt = 0; mt < 2; mt++) {
#pragma unroll
            for (int nt = 0; nt < 8; nt++) {
                int row = wm + mt * 16 + grp;
                int col = wn + nt * 8 + 2 * qid;
                size_t g0 = (m0 + row) * (size_t)ldc + col;
                size_t g2 = (m0 + row + 8) * (size_t)ldc + col;
                *(float2*)(C + g0) = make_float2(acc[mt][nt][0], acc[mt][nt][1]);
                *(float2*)(C + g2) = make_float2(acc[mt][nt][2], acc[mt][nt][3]);
            }
        }
    }
}

// chunk cb covers within-batch M-tiles [TPC*cb, TPC*(cb+1)) for every batch
__global__ void __launch_bounds__(256)
gk_au(const float* __restrict__ t_in, const float* __restrict__ F_in,
      const float* __restrict__ V_r, const float* __restrict__ V_b,
      const float* __restrict__ W_l, const float* __restrict__ b_l,
      float* __restrict__ a_out, float* __restrict__ u_out, int cb) {
    extern __shared__ unsigned sm[];
    int batch = blockIdx.x / TPC;
    int tile  = batch * 32 + (blockIdx.x % TPC) + cb * TPC;
    if (blockIdx.y == 0)
        gemm_body_longk<0>(t_in, nullptr, V_r, W_l, b_l, a_out, sm, tile);
    else
        gemm_body_longk<1>(t_in, F_in, V_b, nullptr, nullptr, u_out, sm, tile);
}

// ---------------- gk_out: K=128 single-shot, t_tilde = s @ V_o + t, time-chunked ----------------
__global__ void __launch_bounds__(256)
gk_out(const float* __restrict__ S, const float* __restrict__ V_o,
       const float* __restrict__ t_in, float* __restrict__ out, int cb) {
    extern __shared__ unsigned sm[];
    unsigned* As = sm;
    unsigned* Bs = sm + 128 * RS;

    const int tid  = threadIdx.x;
    const int wid  = tid >> 5;
    const int lane = tid & 31;
    const int grp  = lane >> 2;
    const int qid  = lane & 3;
    const int wm   = (wid & 3) * 32;
    const int wn   = (wid >> 2) * 64;
    int batch = blockIdx.x / TPC;
    int tile  = batch * 32 + (blockIdx.x % TPC) + cb * TPC;
    const size_t m0 = (size_t)tile * BM;
    const int    n0 = blockIdx.y * BN;

#pragma unroll
    for (int i = 0; i < 16; i++) {
        int idx = tid + i * 256;
        int row = idx >> 5;
        int c4  = (idx & 31) << 2;
        float4 v = *(const float4*)(S + (m0 + row) * (size_t)RDIM + c4);
        *(uint4*)&As[row * RS + c4] =
            make_uint4(f2tf(v.x), f2tf(v.y), f2tf(v.z), f2tf(v.w));
        float4 w = *(const float4*)(V_o + (size_t)row * PDIM + n0 + c4);
        *(uint4*)&Bs[row * RS + c4] =
            make_uint4(f2tf(w.x), f2tf(w.y), f2tf(w.z), f2tf(w.w));
    }
    __syncthreads();

    float acc[2][8][4];
#pragma unroll
    for (int mt = 0; mt < 2; mt++)
#pragma unroll
        for (int nt = 0; nt < 8; nt++)
#pragma unroll
            for (int i = 0; i < 4; i++) acc[mt][nt][i] = 0.0f;

#pragma unroll
    for (int ks = 0; ks < 16; ks++) {
        const int k = ks * 8;
        unsigned af[2][4];
#pragma unroll
        for (int mt = 0; mt < 2; mt++) {
            const unsigned* p = As + (wm + mt * 16 + grp) * RS + k + qid;
            af[mt][0] = p[0];
            af[mt][1] = p[8 * RS];
            af[mt][2] = p[4];
            af[mt][3] = p[8 * RS + 4];
        }
        unsigned bf[8][2];
#pragma unroll
        for (int nt = 0; nt < 8; nt++) {
            const unsigned* p = Bs + (k + qid) * RS + wn + nt * 8 + grp;
            bf[nt][0] = p[0];
            bf[nt][1] = p[4 * RS];
        }
#pragma unroll
        for (int mt = 0; mt < 2; mt++)
#pragma unroll
            for (int nt = 0; nt < 8; nt++)
                mma_tf32(acc[mt][nt], af[mt], bf[nt]);
    }

#pragma unroll
    for (int mt = 0; mt < 2; mt++) {
#pragma unroll
        for (int nt = 0; nt < 8; nt++) {
            int row = wm + mt * 16 + grp;
            int col = wn + nt * 8 + 2 * qid;
            size_t g0 = (m0 + row) * (size_t)PDIM + n0 + col;
            size_t g2 = (m0 + row + 8) * (size_t)PDIM + n0 + col;
            float2 r0 = *(const float2*)(t_in + g0);
            float2 r2 = *(const float2*)(t_in + g2);
            *(float2*)(out + g0) = make_float2(acc[mt][nt][0] + r0.x, acc[mt][nt][1] + r0.y);
            *(float2*)(out + g2) = make_float2(acc[mt][nt][2] + r2.x, acc[mt][nt][3] + r2.y);
        }
    }
}

// ---------------- scan v4: Q-recurrence on v3 lean skeleton ----------------
// Recurrence: p_t = a_{t+1}.*w_t ; w_{t+1} = p_t*inv_t + u_{t+1}
//   Q_{t+1} = inv_t^2*A_t + 2*inv_t*B_t + C_{t+1}
//   A_t = sum(p_t^2), B_t = sum(p_t.*u_{t+1}), C_t = sum(u_t^2)
// Shuffle chains for A_t,B_t are issued at iteration t-1 (right after p_t is
// formed) and consumed at iteration t — one full step of slack. C chains are
// issued at refill — eight steps of slack. Serial per-step path: rsqrt + FMAs.
__device__ __forceinline__ float4 f4mul(float4 a, float4 b) {
    return make_float4(a.x*b.x, a.y*b.y, a.z*b.z, a.w*b.w);
}
__device__ __forceinline__ float4 f4fms(float4 p, float s, float4 u) {
    return make_float4(fmaf(p.x,s,u.x), fmaf(p.y,s,u.y), fmaf(p.z,s,u.z), fmaf(p.w,s,u.w));
}
__device__ __forceinline__ float4 f4sc(float4 a, float s) {
    return make_float4(a.x*s, a.y*s, a.z*s, a.w*s);
}
__device__ __forceinline__ float ssq4(float4 a) {
    float q0 = fmaf(a.y, a.y, a.x * a.x);
    float q1 = fmaf(a.w, a.w, a.z * a.z);
    return q0 + q1;
}
__device__ __forceinline__ float dot4(float4 a, float4 b) {
    float q0 = fmaf(a.y, b.y, a.x * b.x);
    float q1 = fmaf(a.w, b.w, a.z * b.z);
    return q0 + q1;
}
__device__ __forceinline__ float red32(float v) {
    v += __shfl_xor_sync(0xffffffffu, v, 1);
    v += __shfl_xor_sync(0xffffffffu, v, 2);
    v += __shfl_xor_sync(0xffffffffu, v, 4);
    v += __shfl_xor_sync(0xffffffffu, v, 8);
    v += __shfl_xor_sync(0xffffffffu, v, 16);
    return v;
}

// 8 blocks x 32 threads; block b = batch b; lane owns elems [lane*4, lane*4+4).
// Chunk [t0,t1): exact w carry via g_state. No branches/guards in main loop.
__global__ void __launch_bounds__(32)
scan_kernel(const float* __restrict__ A, const float* __restrict__ U,
            float* __restrict__ S, float* __restrict__ cache,
            float* __restrict__ state, int t0, int t1) {
    const int lane = threadIdx.x;
    const int b    = blockIdx.x;
    const size_t base = (size_t)b * TLEN * RDIM + lane * 4;
    const float4* Ap = (const float4*)(A + base);     // row stride = 32 float4
    const float4* Up = (const float4*)(U + base);
    float4*       Sp = (float4*)(S + base);
    const float r128 = 1.0f / 128.0f;

    float4 w;
    if (t0 == 0) {
        w = Up[0];                                     // w_0 = u_0
    } else {
        // recompute inv_{t0-1} from saved w_{t0-1}, advance one step to w_{t0}
        float4 v = *(const float4*)(state + (size_t)b * RDIM + lane * 4);
        float q = red32(ssq4(v));
        float inv0 = rsqrtf(fmaf(q, r128, EPS_V));
        w = f4fms(f4mul(Ap[(size_t)t0 * 32], v), inv0, Up[(size_t)t0 * 32]);
    }
    float Q = red32(ssq4(w));                          // Q_{t0}

    // slot j (tt ≡ j mod 8): qu[j] = u_{tt+1}, qa[j] = a_{tt+2}, qc[j] = C_{tt+1}
    float4 qa[8], qu[8]; float qc[8];
#pragma unroll
    for (int j = 0; j < 8; j++) {
        qu[j] = Up[(size_t)(t0 + 1 + j) * 32];
        qa[j] = Ap[(size_t)(t0 + 2 + j) * 32];
    }
#pragma unroll
    for (int j = 0; j < 8; j++) qc[j] = red32(ssq4(qu[j]));

    // prologue: p_{t0} = a_{t0+1} .* w_{t0}; A_{t0}, B_{t0}
    float4 p = f4mul(Ap[(size_t)(t0 + 1) * 32], w);
    float Aprev = red32(ssq4(p));
    float Bprev = red32(dot4(p, qu[0]));

    int t = t0;
    // main loop: branchless; refills unconditional (max read index tt+10 <= t1-15)
    for (; t < t1 - 24; t += 8) {
#pragma unroll
        for (int j = 0; j < 8; j++) {
            const int tt = t + j;
            float inv = rsqrtf(fmaf(Q, r128, EPS_V));      // inv_tt (serial path)
            Sp[(size_t)tt * 32] = f4sc(w, inv);            // s_tt
            w = f4fms(p, inv, qu[j]);                      // w_{tt+1}
            p = f4mul(qa[j], w);                           // p_{tt+1} = a_{tt+2} .* w_{tt+1}
            const int jn = (j + 1) & 7;
            float nA = red32(ssq4(p));                     // chain -> A_{tt+1} (consumed next iter)
            float nB = red32(dot4(p, qu[jn]));             // chain -> B_{tt+1}
            Q = fmaf(inv * inv, Aprev, fmaf(2.0f * inv, Bprev, qc[j]));  // Q_{tt+1}
            Aprev = nA; Bprev = nB;
            // refill slot j for step tt+8
            qu[j] = Up[(size_t)(tt + 9) * 32];
            qa[j] = Ap[(size_t)(tt + 10) * 32];
            qc[j] = red32(ssq4(qu[j]));                    // chain, 8 steps of slack
        }
    }
    // tail: clamped refills (clamped values feed only dead lanes beyond t1-1)
    for (; t < t1; t += 8) {
#pragma unroll
        for (int j = 0; j < 8; j++) {
            const int tt = t + j;
            float inv = rsqrtf(fmaf(Q, r128, EPS_V));
            float4 s = f4sc(w, inv);
            Sp[(size_t)tt * 32] = s;
            if (tt == t1 - 1) {
                if (t1 == TLEN) {
                    *(float4*)(cache + (size_t)b * RDIM + lane * 4) = s;
                } else {
                    *(float4*)(state + (size_t)b * RDIM + lane * 4) = w;  // save w_{t1-1}
                }
                break;
            }
            w = f4fms(p, inv, qu[j]);
            p = f4mul(qa[j], w);
            const int jn = (j + 1) & 7;
            float nA = red32(ssq4(p));
            float nB = red32(dot4(p, qu[jn]));
            Q = fmaf(inv * inv, Aprev, fmaf(2.0f * inv, Bprev, qc[j]));
            Aprev = nA; Bprev = nB;
            int i9  = tt + 9  < t1 ? tt + 9  : t1 - 1;
            int i10 = tt + 10 < t1 ? tt + 10 : t1 - 1;
            qu[j] = Up[(size_t)i9 * 32];
            qa[j] = Ap[(size_t)i10 * 32];
            qc[j] = red32(ssq4(qu[j]));
        }
    }
}

// ---------------- pipeline resources (created at load time) ----------------
struct PipeRes {
    cudaStream_t s1;
    cudaEvent_t eFork, eA[NCHUNK], eS[NCHUNK], eO;
    PipeRes() {
        cudaStreamCreateWithFlags(&s1, cudaStreamNonBlocking);
        cudaEventCreateWithFlags(&eFork, cudaEventDisableTiming);
        for (int i = 0; i < NCHUNK; i++) {
            cudaEventCreateWithFlags(&eA[i], cudaEventDisableTiming);
            cudaEventCreateWithFlags(&eS[i], cudaEventDisableTiming);
        }
        cudaEventCreateWithFlags(&eO, cudaEventDisableTiming);
    }
};
static PipeRes g_pipe;

extern "C" void kernel_launch(void* const* d_in, const int* in_sizes, int n_in,
                              void* d_out, int out_size) {
    const float* t_in = (const float*)d_in[0];
    const float* F_in = (const float*)d_in[1];
    const float* V_r  = (const float*)d_in[2];
    const float* V_b  = (const float*)d_in[3];
    const float* V_o  = (const float*)d_in[4];
    const float* W_l  = (const float*)d_in[5];
    const float* b_l  = (const float*)d_in[6];
    float* out = (float*)d_out;

    float *u, *a, *s, *st;
    cudaGetSymbolAddress((void**)&u,  g_u);
    cudaGetSymbolAddress((void**)&a,  g_a);
    cudaGetSymbolAddress((void**)&s,  g_s);
    cudaGetSymbolAddress((void**)&st, g_state);
    float* cache = out + (size_t)MROWS * PDIM;

    cudaFuncSetAttribute(gk_au,  cudaFuncAttributeMaxDynamicSharedMemorySize, SMEM_BYTES_FUSED);
    cudaFuncSetAttribute(gk_out, cudaFuncAttributeMaxDynamicSharedMemorySize, SMEM_BYTES_OUT);

    cudaStream_t d = 0, s1 = g_pipe.s1;
    dim3 blk(256);
    dim3 gAU(BATCH * TPC, 2);
    dim3 gOUT(BATCH * TPC, PDIM / BN);

    // fork
    cudaEventRecord(g_pipe.eFork, d);
    cudaStreamWaitEvent(s1, g_pipe.eFork, 0);

    // chunk-0 producer on main stream; chunks 1..N-1 on side stream
    gk_au<<<gAU, blk, SMEM_BYTES_FUSED, d>>>(t_in, F_in, V_r, V_b, W_l, b_l, a, u, 0);
    for (int c = 1; c < NCHUNK; c++) {
        gk_au<<<gAU, blk, SMEM_BYTES_FUSED, s1>>>(t_in, F_in, V_r, V_b, W_l, b_l, a, u, c);
        cudaEventRecord(g_pipe.eA[c], s1);
    }

    // scans on main stream; gk_out consumers on side stream (except the last)
    for (int c = 0; c < NCHUNK; c++) {
        if (c > 0) cudaStreamWaitEvent(d, g_pipe.eA[c], 0);
        scan_kernel<<<BATCH, 32, 0, d>>>(a, u, s, cache, st, c * TCHUNK, (c + 1) * TCHUNK);
        if (c < NCHUNK - 1) {
            cudaEventRecord(g_pipe.eS[c], d);
            cudaStreamWaitEvent(s1, g_pipe.eS[c], 0);
            gk_out<<<gOUT, blk, SMEM_BYTES_OUT, s1>>>(s, V_o, t_in, out, c);
            if (c == NCHUNK - 2) cudaEventRecord(g_pipe.eO, s1);
        }
    }
    // last consumer on main stream
    gk_out<<<gOUT, blk, SMEM_BYTES_OUT, d>>>(s, V_o, t_in, out, NCHUNK - 1);

    // join
    cudaStreamWaitEvent(d, g_pipe.eO, 0);
}